// round 6
// baseline (speedup 1.0000x reference)
#include <cuda_runtime.h>
#include <cstdint>

// StateObsMLP: B=2048 rows, C=32 categories.
//   obs_emb  = obs(512)   @ obs_W(512x256)        + obs_b
//   state_emb= relu(state(64) @ state_W[c](64x256) + state_b[c])
//   out      = concat(state_emb, obs_emb)(512) @ l2_W[c](512x256) + l2_b[c]
//
// R5: exact tile worklist + 148 persistent CTAs (single balanced wave),
// float4-vectorized A-operand smem loads (LDS wavefronts per k-iter 8 -> 5).
// Keeps R3's 512-thread K-parity split with group-scoped named barriers.

#define CATS     32
#define SDIM     64
#define EMB      256
#define ODIM     512
#define XDIM     512
#define MT       16     // rows per tile
#define KC       16     // K-chunk
#define KCE      (KC * EMB)   // floats per chunk buffer (4096)
#define NTHREADS 512
#define B_MAX    2048
#define MAX_TILES (CATS + B_MAX / MT)   // 160
#define NCTAS    148

__device__ int g_perm[B_MAX];
__device__ int g_cat_start[CATS + 1];
__device__ int g_tiles[MAX_TILES];
__device__ int g_ntiles;

// ---------------------------------------------------------------------------
// Kernel 1: bin rows by category + build flattened (cat, tile) worklist.
// ---------------------------------------------------------------------------
__global__ void bin_kernel(const int* __restrict__ cat, int B) {
    __shared__ int cnt[CATS];
    __shared__ int st[CATS + 1];
    __shared__ int cur[CATS];
    int t = threadIdx.x;
    if (t < CATS) cnt[t] = 0;
    __syncthreads();
    for (int b = t; b < B; b += blockDim.x) atomicAdd(&cnt[cat[b]], 1);
    __syncthreads();
    if (t == 0) {
        int s = 0;
        for (int c = 0; c < CATS; c++) { st[c] = s; s += cnt[c]; }
        st[CATS] = s;
        // flattened worklist: one entry per (category, 16-row tile)
        int n = 0;
        for (int c = 0; c < CATS; c++) {
            int nt = (cnt[c] + MT - 1) / MT;
            for (int i = 0; i < nt; i++) g_tiles[n++] = (c << 16) | i;
        }
        g_ntiles = n;
    }
    __syncthreads();
    if (t < CATS) cur[t] = st[t];
    __syncthreads();
    for (int b = t; b < B; b += blockDim.x) {
        int pos = atomicAdd(&cur[cat[b]], 1);
        g_perm[pos] = b;
    }
    if (t <= CATS) g_cat_start[t] = st[t];
}

// ---------------------------------------------------------------------------
// Group-split GEMM: this thread's group handles chunks first, first+2, ...
// ---------------------------------------------------------------------------
__device__ __forceinline__ void grp_bar(int barid) {
    asm volatile("bar.sync %0, %1;" :: "r"(barid), "r"(256) : "memory");
}

__device__ __forceinline__ void gemm_split(
    const float* __restrict__ A, int lda,
    const float* __restrict__ W, int K,
    float* wb0, float* wb1,
    int first, int barid,
    int gt, int r0, int c64, float4 acc[4])
{
    const float4* Wv = (const float4*)W;
    int nch = K / KC;            // always even (4 or 32)
    int count = nch >> 1;        // chunks this group owns
    // prologue: chunk `first` -> wb0
    {
        const float4* src = Wv + (size_t)first * (KCE / 4);
        uint32_t dst = (uint32_t)__cvta_generic_to_shared(wb0);
        #pragma unroll
        for (int i = gt; i < KCE / 4; i += 256)
            asm volatile("cp.async.cg.shared.global [%0], [%1], 16;"
                         :: "r"(dst + i * 16), "l"(src + i));
        asm volatile("cp.async.commit_group;");
    }
    for (int j = 0; j < count; j++) {
        int ch = first + 2 * j;
        float* wb = (j & 1) ? wb1 : wb0;
        if (j + 1 < count) {
            float* nb = (j & 1) ? wb0 : wb1;
            const float4* src = Wv + (size_t)(ch + 2) * (KCE / 4);
            uint32_t dst = (uint32_t)__cvta_generic_to_shared(nb);
            #pragma unroll
            for (int i = gt; i < KCE / 4; i += 256)
                asm volatile("cp.async.cg.shared.global [%0], [%1], 16;"
                             :: "r"(dst + i * 16), "l"(src + i));
            asm volatile("cp.async.commit_group;");
            asm volatile("cp.async.wait_group 1;");
        } else {
            asm volatile("cp.async.wait_group 0;");
        }
        grp_bar(barid);
        const float* A0 = A + (r0 + 0) * lda + ch * KC;
        const float* A1 = A0 + lda;
        const float* A2 = A1 + lda;
        const float* A3 = A2 + lda;
        const float4* Wrow = (const float4*)wb + c64;
        #pragma unroll
        for (int kk = 0; kk < KC; kk += 4) {
            // one LDS.128 broadcast per row per 4 k-steps (vs 4 LDS.32)
            float4 a0 = *(const float4*)(A0 + kk);
            float4 a1 = *(const float4*)(A1 + kk);
            float4 a2 = *(const float4*)(A2 + kk);
            float4 a3 = *(const float4*)(A3 + kk);
            #pragma unroll
            for (int u = 0; u < 4; u++) {
                float b0 = (&a0.x)[u];
                float b1 = (&a1.x)[u];
                float b2 = (&a2.x)[u];
                float b3 = (&a3.x)[u];
                float4 w = Wrow[(kk + u) * 64];
                acc[0].x = fmaf(b0, w.x, acc[0].x);
                acc[0].y = fmaf(b0, w.y, acc[0].y);
                acc[0].z = fmaf(b0, w.z, acc[0].z);
                acc[0].w = fmaf(b0, w.w, acc[0].w);
                acc[1].x = fmaf(b1, w.x, acc[1].x);
                acc[1].y = fmaf(b1, w.y, acc[1].y);
                acc[1].z = fmaf(b1, w.z, acc[1].z);
                acc[1].w = fmaf(b1, w.w, acc[1].w);
                acc[2].x = fmaf(b2, w.x, acc[2].x);
                acc[2].y = fmaf(b2, w.y, acc[2].y);
                acc[2].z = fmaf(b2, w.z, acc[2].z);
                acc[2].w = fmaf(b2, w.w, acc[2].w);
                acc[3].x = fmaf(b3, w.x, acc[3].x);
                acc[3].y = fmaf(b3, w.y, acc[3].y);
                acc[3].z = fmaf(b3, w.z, acc[3].z);
                acc[3].w = fmaf(b3, w.w, acc[3].w);
            }
        }
        grp_bar(barid);  // buffer wb will be overwritten at j+1's prefetch
    }
}

// ---------------------------------------------------------------------------
// Kernel 2: persistent CTAs over the tile worklist, 512 threads, K-split.
// smem (floats): s_s 1024 | o_s 8192 | x_s 8192 | w[4][4096] | red 4096
// ---------------------------------------------------------------------------
#define SMEM_FLOATS (MT*SDIM + MT*ODIM + MT*XDIM + 4*KCE + MT*EMB)

__global__ __launch_bounds__(NTHREADS, 1)
void fused_kernel(const float* __restrict__ state,
                  const float* __restrict__ obs,
                  const float* __restrict__ obs_W,
                  const float* __restrict__ obs_b,
                  const float* __restrict__ state_W,
                  const float* __restrict__ state_b,
                  const float* __restrict__ l2_W,
                  const float* __restrict__ l2_b,
                  float* __restrict__ out)
{
    extern __shared__ float sm[];
    __shared__ int rows_sh[MT];
    float* s_s = sm;                        // 16 x 64
    float* o_s = s_s + MT * SDIM;           // 16 x 512
    float* x_s = o_s + MT * ODIM;           // 16 x 512 (concat target)
    float* wB  = x_s + MT * XDIM;           // 4 buffers of KCE
    float* red = wB + 4 * KCE;              // 16 x 256 reduction staging

    int t    = threadIdx.x;
    int grp  = t >> 8;              // 0 or 1
    int gt   = t & 255;
    int r0   = (gt >> 6) << 2;      // 0,4,8,12
    int c64  = gt & 63;             // float4 column index
    int barid = 1 + grp;
    float* wb0 = wB + grp * 2 * KCE;
    float* wb1 = wb0 + KCE;

    int NT = g_ntiles;

    for (int widx = blockIdx.x; widx < NT; widx += gridDim.x) {
        __syncthreads();            // protect rows_sh / smem from prev tile
        int ent  = g_tiles[widx];
        int g    = ent >> 16;
        int tile = ent & 0xFFFF;
        int start = g_cat_start[g];
        int cnt   = g_cat_start[g + 1] - start;
        int base  = start + tile * MT;
        if (t < MT) rows_sh[t] = (tile * MT + t < cnt) ? g_perm[base + t] : -1;
        __syncthreads();

        // gather state rows: 16x64 = 256 float4
        if (t < 256) {
            int r = t >> 4, c4 = t & 15;
            int row = rows_sh[r];
            float4 v = make_float4(0.f, 0.f, 0.f, 0.f);
            if (row >= 0) v = ((const float4*)state)[row * 16 + c4];
            ((float4*)s_s)[t] = v;
        }
        // gather obs rows: 16x512 = 2048 float4
        #pragma unroll
        for (int i = t; i < MT * 128; i += NTHREADS) {
            int r = i >> 7, c4 = i & 127;
            int row = rows_sh[r];
            float4 v = make_float4(0.f, 0.f, 0.f, 0.f);
            if (row >= 0) v = ((const float4*)obs)[row * 128 + c4];
            ((float4*)o_s)[i] = v;
        }
        __syncthreads();

        float4 acc[4];
        float4* redv = (float4*)red;

        // --- Phase A: state_emb = relu(state @ state_W[g] + state_b[g]) ---
        acc[0] = acc[1] = acc[2] = acc[3] = make_float4(0.f, 0.f, 0.f, 0.f);
        gemm_split(s_s, SDIM, state_W + (size_t)g * SDIM * EMB, SDIM,
                   wb0, wb1, grp, barid, gt, r0, c64, acc);
        __syncthreads();
        if (grp == 1) {
            #pragma unroll
            for (int ri = 0; ri < 4; ri++) redv[(r0 + ri) * 64 + c64] = acc[ri];
        }
        __syncthreads();
        if (grp == 0) {
            float4 bb = ((const float4*)(state_b + g * EMB))[c64];
            #pragma unroll
            for (int ri = 0; ri < 4; ri++) {
                float4 p = redv[(r0 + ri) * 64 + c64];
                float4 v;
                v.x = fmaxf(acc[ri].x + p.x + bb.x, 0.f);
                v.y = fmaxf(acc[ri].y + p.y + bb.y, 0.f);
                v.z = fmaxf(acc[ri].z + p.z + bb.z, 0.f);
                v.w = fmaxf(acc[ri].w + p.w + bb.w, 0.f);
                ((float4*)(x_s + (r0 + ri) * XDIM))[c64] = v;
            }
        }
        __syncthreads();   // red free; x_s cols [0,256) written

        // --- Phase B: obs_emb = obs @ obs_W + obs_b -> x cols [256,512) ---
        acc[0] = acc[1] = acc[2] = acc[3] = make_float4(0.f, 0.f, 0.f, 0.f);
        gemm_split(o_s, ODIM, obs_W, ODIM,
                   wb0, wb1, grp, barid, gt, r0, c64, acc);
        __syncthreads();
        if (grp == 1) {
            #pragma unroll
            for (int ri = 0; ri < 4; ri++) redv[(r0 + ri) * 64 + c64] = acc[ri];
        }
        __syncthreads();
        if (grp == 0) {
            float4 bb = ((const float4*)obs_b)[c64];
            #pragma unroll
            for (int ri = 0; ri < 4; ri++) {
                float4 p = redv[(r0 + ri) * 64 + c64];
                float4 v;
                v.x = acc[ri].x + p.x + bb.x;
                v.y = acc[ri].y + p.y + bb.y;
                v.z = acc[ri].z + p.z + bb.z;
                v.w = acc[ri].w + p.w + bb.w;
                ((float4*)(x_s + (r0 + ri) * XDIM + EMB))[c64] = v;
            }
        }
        __syncthreads();   // x_s complete

        // --- Phase C: out = x @ l2_W[g] + l2_b[g], scatter ---
        acc[0] = acc[1] = acc[2] = acc[3] = make_float4(0.f, 0.f, 0.f, 0.f);
        gemm_split(x_s, XDIM, l2_W + (size_t)g * XDIM * EMB, XDIM,
                   wb0, wb1, grp, barid, gt, r0, c64, acc);
        __syncthreads();
        if (grp == 1) {
            #pragma unroll
            for (int ri = 0; ri < 4; ri++) redv[(r0 + ri) * 64 + c64] = acc[ri];
        }
        __syncthreads();
        if (grp == 0) {
            float4 bb = ((const float4*)(l2_b + g * EMB))[c64];
            #pragma unroll
            for (int ri = 0; ri < 4; ri++) {
                int row = rows_sh[r0 + ri];
                if (row >= 0) {
                    float4 p = redv[(r0 + ri) * 64 + c64];
                    float4 v;
                    v.x = acc[ri].x + p.x + bb.x;
                    v.y = acc[ri].y + p.y + bb.y;
                    v.z = acc[ri].z + p.z + bb.z;
                    v.w = acc[ri].w + p.w + bb.w;
                    ((float4*)(out + (size_t)row * EMB))[c64] = v;
                }
            }
        }
    }
}

// ---------------------------------------------------------------------------
extern "C" void kernel_launch(void* const* d_in, const int* in_sizes, int n_in,
                              void* d_out, int out_size) {
    const float* state   = (const float*)d_in[0];
    const float* obs     = (const float*)d_in[1];
    const int*   cat_ids = (const int*)  d_in[2];
    const float* obs_W   = (const float*)d_in[3];
    const float* obs_b   = (const float*)d_in[4];
    const float* state_W = (const float*)d_in[5];
    const float* state_b = (const float*)d_in[6];
    const float* l2_W    = (const float*)d_in[7];
    const float* l2_b    = (const float*)d_in[8];
    float* out = (float*)d_out;

    int B = in_sizes[2];

    size_t smem_bytes = SMEM_FLOATS * sizeof(float);  // 151552
    cudaFuncSetAttribute(fused_kernel,
                         cudaFuncAttributeMaxDynamicSharedMemorySize,
                         (int)smem_bytes);

    bin_kernel<<<1, 256>>>(cat_ids, B);

    fused_kernel<<<NCTAS, NTHREADS, smem_bytes>>>(
        state, obs, obs_W, obs_b, state_W, state_b, l2_W, l2_b, out);
}

// round 7
// speedup vs baseline: 1.0105x; 1.0105x over previous
#include <cuda_runtime.h>
#include <cstdint>

// StateObsMLP: B=2048 rows, C=32 categories.
//   obs_emb  = obs(512)   @ obs_W(512x256)        + obs_b
//   state_emb= relu(state(64) @ state_W[c](64x256) + state_b[c])
//   out      = concat(state_emb, obs_emb)(512) @ l2_W[c](512x256) + l2_b[c]
//
// R5: exact tile worklist + 148 persistent CTAs (single balanced wave),
// float4-vectorized A-operand smem loads (LDS wavefronts per k-iter 8 -> 5).
// Keeps R3's 512-thread K-parity split with group-scoped named barriers.

#define CATS     32
#define SDIM     64
#define EMB      256
#define ODIM     512
#define XDIM     512
#define MT       16     // rows per tile
#define KC       16     // K-chunk
#define KCE      (KC * EMB)   // floats per chunk buffer (4096)
#define NTHREADS 512
#define B_MAX    2048
#define MAX_TILES (CATS + B_MAX / MT)   // 160
#define NCTAS    148

__device__ int g_perm[B_MAX];
__device__ int g_cat_start[CATS + 1];
__device__ int g_tiles[MAX_TILES];
__device__ int g_ntiles;

// ---------------------------------------------------------------------------
// Kernel 1: bin rows by category + build flattened (cat, tile) worklist.
// ---------------------------------------------------------------------------
__global__ void bin_kernel(const int* __restrict__ cat, int B) {
    __shared__ int cnt[CATS];
    __shared__ int st[CATS + 1];
    __shared__ int cur[CATS];
    int t = threadIdx.x;
    if (t < CATS) cnt[t] = 0;
    __syncthreads();
    for (int b = t; b < B; b += blockDim.x) atomicAdd(&cnt[cat[b]], 1);
    __syncthreads();
    if (t == 0) {
        int s = 0;
        for (int c = 0; c < CATS; c++) { st[c] = s; s += cnt[c]; }
        st[CATS] = s;
        // flattened worklist: one entry per (category, 16-row tile)
        int n = 0;
        for (int c = 0; c < CATS; c++) {
            int nt = (cnt[c] + MT - 1) / MT;
            for (int i = 0; i < nt; i++) g_tiles[n++] = (c << 16) | i;
        }
        g_ntiles = n;
    }
    __syncthreads();
    if (t < CATS) cur[t] = st[t];
    __syncthreads();
    for (int b = t; b < B; b += blockDim.x) {
        int pos = atomicAdd(&cur[cat[b]], 1);
        g_perm[pos] = b;
    }
    if (t <= CATS) g_cat_start[t] = st[t];
}

// ---------------------------------------------------------------------------
// Group-split GEMM: this thread's group handles chunks first, first+2, ...
// ---------------------------------------------------------------------------
__device__ __forceinline__ void grp_bar(int barid) {
    asm volatile("bar.sync %0, %1;" :: "r"(barid), "r"(256) : "memory");
}

__device__ __forceinline__ void gemm_split(
    const float* __restrict__ A, int lda,
    const float* __restrict__ W, int K,
    float* wb0, float* wb1,
    int first, int barid,
    int gt, int r0, int c64, float4 acc[4])
{
    const float4* Wv = (const float4*)W;
    int nch = K / KC;            // always even (4 or 32)
    int count = nch >> 1;        // chunks this group owns
    // prologue: chunk `first` -> wb0
    {
        const float4* src = Wv + (size_t)first * (KCE / 4);
        uint32_t dst = (uint32_t)__cvta_generic_to_shared(wb0);
        #pragma unroll
        for (int i = gt; i < KCE / 4; i += 256)
            asm volatile("cp.async.cg.shared.global [%0], [%1], 16;"
                         :: "r"(dst + i * 16), "l"(src + i));
        asm volatile("cp.async.commit_group;");
    }
    for (int j = 0; j < count; j++) {
        int ch = first + 2 * j;
        float* wb = (j & 1) ? wb1 : wb0;
        if (j + 1 < count) {
            float* nb = (j & 1) ? wb0 : wb1;
            const float4* src = Wv + (size_t)(ch + 2) * (KCE / 4);
            uint32_t dst = (uint32_t)__cvta_generic_to_shared(nb);
            #pragma unroll
            for (int i = gt; i < KCE / 4; i += 256)
                asm volatile("cp.async.cg.shared.global [%0], [%1], 16;"
                             :: "r"(dst + i * 16), "l"(src + i));
            asm volatile("cp.async.commit_group;");
            asm volatile("cp.async.wait_group 1;");
        } else {
            asm volatile("cp.async.wait_group 0;");
        }
        grp_bar(barid);
        const float* A0 = A + (r0 + 0) * lda + ch * KC;
        const float* A1 = A0 + lda;
        const float* A2 = A1 + lda;
        const float* A3 = A2 + lda;
        const float4* Wrow = (const float4*)wb + c64;
        #pragma unroll
        for (int kk = 0; kk < KC; kk += 4) {
            // one LDS.128 broadcast per row per 4 k-steps (vs 4 LDS.32)
            float4 a0 = *(const float4*)(A0 + kk);
            float4 a1 = *(const float4*)(A1 + kk);
            float4 a2 = *(const float4*)(A2 + kk);
            float4 a3 = *(const float4*)(A3 + kk);
            #pragma unroll
            for (int u = 0; u < 4; u++) {
                float b0 = (&a0.x)[u];
                float b1 = (&a1.x)[u];
                float b2 = (&a2.x)[u];
                float b3 = (&a3.x)[u];
                float4 w = Wrow[(kk + u) * 64];
                acc[0].x = fmaf(b0, w.x, acc[0].x);
                acc[0].y = fmaf(b0, w.y, acc[0].y);
                acc[0].z = fmaf(b0, w.z, acc[0].z);
                acc[0].w = fmaf(b0, w.w, acc[0].w);
                acc[1].x = fmaf(b1, w.x, acc[1].x);
                acc[1].y = fmaf(b1, w.y, acc[1].y);
                acc[1].z = fmaf(b1, w.z, acc[1].z);
                acc[1].w = fmaf(b1, w.w, acc[1].w);
                acc[2].x = fmaf(b2, w.x, acc[2].x);
                acc[2].y = fmaf(b2, w.y, acc[2].y);
                acc[2].z = fmaf(b2, w.z, acc[2].z);
                acc[2].w = fmaf(b2, w.w, acc[2].w);
                acc[3].x = fmaf(b3, w.x, acc[3].x);
                acc[3].y = fmaf(b3, w.y, acc[3].y);
                acc[3].z = fmaf(b3, w.z, acc[3].z);
                acc[3].w = fmaf(b3, w.w, acc[3].w);
            }
        }
        grp_bar(barid);  // buffer wb will be overwritten at j+1's prefetch
    }
}

// ---------------------------------------------------------------------------
// Kernel 2: persistent CTAs over the tile worklist, 512 threads, K-split.
// smem (floats): s_s 1024 | o_s 8192 | x_s 8192 | w[4][4096] | red 4096
// ---------------------------------------------------------------------------
#define SMEM_FLOATS (MT*SDIM + MT*ODIM + MT*XDIM + 4*KCE + MT*EMB)

__global__ __launch_bounds__(NTHREADS, 1)
void fused_kernel(const float* __restrict__ state,
                  const float* __restrict__ obs,
                  const float* __restrict__ obs_W,
                  const float* __restrict__ obs_b,
                  const float* __restrict__ state_W,
                  const float* __restrict__ state_b,
                  const float* __restrict__ l2_W,
                  const float* __restrict__ l2_b,
                  float* __restrict__ out)
{
    extern __shared__ float sm[];
    __shared__ int rows_sh[MT];
    float* s_s = sm;                        // 16 x 64
    float* o_s = s_s + MT * SDIM;           // 16 x 512
    float* x_s = o_s + MT * ODIM;           // 16 x 512 (concat target)
    float* wB  = x_s + MT * XDIM;           // 4 buffers of KCE
    float* red = wB + 4 * KCE;              // 16 x 256 reduction staging

    int t    = threadIdx.x;
    int grp  = t >> 8;              // 0 or 1
    int gt   = t & 255;
    int r0   = (gt >> 6) << 2;      // 0,4,8,12
    int c64  = gt & 63;             // float4 column index
    int barid = 1 + grp;
    float* wb0 = wB + grp * 2 * KCE;
    float* wb1 = wb0 + KCE;

    int NT = g_ntiles;

    for (int widx = blockIdx.x; widx < NT; widx += gridDim.x) {
        __syncthreads();            // protect rows_sh / smem from prev tile
        int ent  = g_tiles[widx];
        int g    = ent >> 16;
        int tile = ent & 0xFFFF;
        int start = g_cat_start[g];
        int cnt   = g_cat_start[g + 1] - start;
        int base  = start + tile * MT;
        if (t < MT) rows_sh[t] = (tile * MT + t < cnt) ? g_perm[base + t] : -1;
        __syncthreads();

        // gather state rows: 16x64 = 256 float4
        if (t < 256) {
            int r = t >> 4, c4 = t & 15;
            int row = rows_sh[r];
            float4 v = make_float4(0.f, 0.f, 0.f, 0.f);
            if (row >= 0) v = ((const float4*)state)[row * 16 + c4];
            ((float4*)s_s)[t] = v;
        }
        // gather obs rows: 16x512 = 2048 float4
        #pragma unroll
        for (int i = t; i < MT * 128; i += NTHREADS) {
            int r = i >> 7, c4 = i & 127;
            int row = rows_sh[r];
            float4 v = make_float4(0.f, 0.f, 0.f, 0.f);
            if (row >= 0) v = ((const float4*)obs)[row * 128 + c4];
            ((float4*)o_s)[i] = v;
        }
        __syncthreads();

        float4 acc[4];
        float4* redv = (float4*)red;

        // --- Phase A: state_emb = relu(state @ state_W[g] + state_b[g]) ---
        acc[0] = acc[1] = acc[2] = acc[3] = make_float4(0.f, 0.f, 0.f, 0.f);
        gemm_split(s_s, SDIM, state_W + (size_t)g * SDIM * EMB, SDIM,
                   wb0, wb1, grp, barid, gt, r0, c64, acc);
        __syncthreads();
        if (grp == 1) {
            #pragma unroll
            for (int ri = 0; ri < 4; ri++) redv[(r0 + ri) * 64 + c64] = acc[ri];
        }
        __syncthreads();
        if (grp == 0) {
            float4 bb = ((const float4*)(state_b + g * EMB))[c64];
            #pragma unroll
            for (int ri = 0; ri < 4; ri++) {
                float4 p = redv[(r0 + ri) * 64 + c64];
                float4 v;
                v.x = fmaxf(acc[ri].x + p.x + bb.x, 0.f);
                v.y = fmaxf(acc[ri].y + p.y + bb.y, 0.f);
                v.z = fmaxf(acc[ri].z + p.z + bb.z, 0.f);
                v.w = fmaxf(acc[ri].w + p.w + bb.w, 0.f);
                ((float4*)(x_s + (r0 + ri) * XDIM))[c64] = v;
            }
        }
        __syncthreads();   // red free; x_s cols [0,256) written

        // --- Phase B: obs_emb = obs @ obs_W + obs_b -> x cols [256,512) ---
        acc[0] = acc[1] = acc[2] = acc[3] = make_float4(0.f, 0.f, 0.f, 0.f);
        gemm_split(o_s, ODIM, obs_W, ODIM,
                   wb0, wb1, grp, barid, gt, r0, c64, acc);
        __syncthreads();
        if (grp == 1) {
            #pragma unroll
            for (int ri = 0; ri < 4; ri++) redv[(r0 + ri) * 64 + c64] = acc[ri];
        }
        __syncthreads();
        if (grp == 0) {
            float4 bb = ((const float4*)obs_b)[c64];
            #pragma unroll
            for (int ri = 0; ri < 4; ri++) {
                float4 p = redv[(r0 + ri) * 64 + c64];
                float4 v;
                v.x = acc[ri].x + p.x + bb.x;
                v.y = acc[ri].y + p.y + bb.y;
                v.z = acc[ri].z + p.z + bb.z;
                v.w = acc[ri].w + p.w + bb.w;
                ((float4*)(x_s + (r0 + ri) * XDIM + EMB))[c64] = v;
            }
        }
        __syncthreads();   // x_s complete

        // --- Phase C: out = x @ l2_W[g] + l2_b[g], scatter ---
        acc[0] = acc[1] = acc[2] = acc[3] = make_float4(0.f, 0.f, 0.f, 0.f);
        gemm_split(x_s, XDIM, l2_W + (size_t)g * XDIM * EMB, XDIM,
                   wb0, wb1, grp, barid, gt, r0, c64, acc);
        __syncthreads();
        if (grp == 1) {
            #pragma unroll
            for (int ri = 0; ri < 4; ri++) redv[(r0 + ri) * 64 + c64] = acc[ri];
        }
        __syncthreads();
        if (grp == 0) {
            float4 bb = ((const float4*)(l2_b + g * EMB))[c64];
            #pragma unroll
            for (int ri = 0; ri < 4; ri++) {
                int row = rows_sh[r0 + ri];
                if (row >= 0) {
                    float4 p = redv[(r0 + ri) * 64 + c64];
                    float4 v;
                    v.x = acc[ri].x + p.x + bb.x;
                    v.y = acc[ri].y + p.y + bb.y;
                    v.z = acc[ri].z + p.z + bb.z;
                    v.w = acc[ri].w + p.w + bb.w;
                    ((float4*)(out + (size_t)row * EMB))[c64] = v;
                }
            }
        }
    }
}

// ---------------------------------------------------------------------------
extern "C" void kernel_launch(void* const* d_in, const int* in_sizes, int n_in,
                              void* d_out, int out_size) {
    const float* state   = (const float*)d_in[0];
    const float* obs     = (const float*)d_in[1];
    const int*   cat_ids = (const int*)  d_in[2];
    const float* obs_W   = (const float*)d_in[3];
    const float* obs_b   = (const float*)d_in[4];
    const float* state_W = (const float*)d_in[5];
    const float* state_b = (const float*)d_in[6];
    const float* l2_W    = (const float*)d_in[7];
    const float* l2_b    = (const float*)d_in[8];
    float* out = (float*)d_out;

    int B = in_sizes[2];

    size_t smem_bytes = SMEM_FLOATS * sizeof(float);  // 151552
    cudaFuncSetAttribute(fused_kernel,
                         cudaFuncAttributeMaxDynamicSharedMemorySize,
                         (int)smem_bytes);

    bin_kernel<<<1, 256>>>(cat_ids, B);

    fused_kernel<<<NCTAS, NTHREADS, smem_bytes>>>(
        state, obs, obs_W, obs_b, state_W, state_b, l2_W, l2_b, out);
}

// round 10
// speedup vs baseline: 1.4805x; 1.4651x over previous
#include <cuda_runtime.h>
#include <cstdint>

// StateObsMLP via mma.sync tf32 (baseline PTX, works at compute_103).
//   obs_emb  = obs(512)   @ obs_W(512x256)        + obs_b
//   state_emb= relu(state(64) @ state_W[c](64x256) + state_b[c])
//   out      = concat(state_emb, obs_emb)(512) @ l2_W[c](512x256) + l2_b[c]
//
// Per (category, 16-row tile) CTA: 8 warps, warp w owns n in [32w, 32w+32).
// All three GEMMs on m16n8k8 tf32 HMMA; weights consumed in native K x N
// row-major layout; K streamed in 32-chunks with double-buffered cp.async.
// R10 fix: COPY_W now fills the FULL 32x256 chunk (2048 float4, was 512).

#define CATS   32
#define EMB    256
#define B_MAX  2048
#define MT     16
#define KC     32
#define NTH    256
#define ASTR   36            // A smem row stride: banks (4*gid+tig)%32 unique
#define WSTR   264           // W smem row stride: banks (8*tig+gid)%32 unique
#define XSTR   516           // x smem row stride: conflict-free A-frag reads
#define MAX_TILES (CATS + B_MAX / MT)
#define NCTAS  148

__device__ int g_perm[B_MAX];
__device__ int g_cat_start[CATS + 1];
__device__ int g_tiles[MAX_TILES];
__device__ int g_ntiles;

// ---------------------------------------------------------------------------
// Kernel 1: bin rows by category + flattened (cat, tile) worklist.
// ---------------------------------------------------------------------------
__global__ void bin_kernel(const int* __restrict__ cat, int B) {
    __shared__ int cnt[CATS];
    __shared__ int st[CATS + 1];
    __shared__ int cur[CATS];
    int t = threadIdx.x;
    if (t < CATS) cnt[t] = 0;
    __syncthreads();
    for (int b = t; b < B; b += blockDim.x) atomicAdd(&cnt[cat[b]], 1);
    __syncthreads();
    if (t == 0) {
        int s = 0;
        for (int c = 0; c < CATS; c++) { st[c] = s; s += cnt[c]; }
        st[CATS] = s;
        int n = 0;
        for (int c = 0; c < CATS; c++) {
            int nt = (cnt[c] + MT - 1) / MT;
            for (int i = 0; i < nt; i++) g_tiles[n++] = (c << 16) | i;
        }
        g_ntiles = n;
    }
    __syncthreads();
    if (t < CATS) cur[t] = st[t];
    __syncthreads();
    for (int b = t; b < B; b += blockDim.x) {
        int pos = atomicAdd(&cur[cat[b]], 1);
        g_perm[pos] = b;
    }
    if (t <= CATS) g_cat_start[t] = st[t];
}

// ---------------------------------------------------------------------------
// mma.sync helpers
// ---------------------------------------------------------------------------
__device__ __forceinline__ uint32_t f2tf(float f) {
    uint32_t u;
    asm("cvt.rna.tf32.f32 %0, %1;" : "=r"(u) : "f"(f));
    return u;
}
__device__ __forceinline__ void mma_tf32(float* c,
    uint32_t a0, uint32_t a1, uint32_t a2, uint32_t a3,
    uint32_t b0, uint32_t b1)
{
    asm volatile(
        "mma.sync.aligned.m16n8k8.row.col.f32.tf32.tf32.f32 "
        "{%0,%1,%2,%3}, {%4,%5,%6,%7}, {%8,%9}, {%0,%1,%2,%3};"
        : "+f"(c[0]), "+f"(c[1]), "+f"(c[2]), "+f"(c[3])
        : "r"(a0), "r"(a1), "r"(a2), "r"(a3), "r"(b0), "r"(b1));
}
__device__ __forceinline__ uint32_t smem_u32(const void* p) {
    uint32_t a;
    asm("{ .reg .u64 t; cvta.to.shared.u64 t, %1; cvt.u32.u64 %0, t; }"
        : "=r"(a) : "l"(p));
    return a;
}
#define CP16(dst, src, sz) \
    asm volatile("cp.async.cg.shared.global [%0], [%1], 16, %2;" \
                 :: "r"(dst), "l"(src), "r"(sz))

// One 32-K chunk of MMAs. Abase: smem row0 at this chunk's k-offset.
__device__ __forceinline__ void chunk_mma(
    const float* __restrict__ Abase, int astride,
    const float* __restrict__ Wbuf,
    int gid, int tig, int nbase, float c[16])
{
    #pragma unroll
    for (int ks = 0; ks < 4; ks++) {
        int k0 = ks * 8;
        uint32_t a0 = f2tf(Abase[gid * astride + k0 + tig]);
        uint32_t a1 = f2tf(Abase[(gid + 8) * astride + k0 + tig]);
        uint32_t a2 = f2tf(Abase[gid * astride + k0 + tig + 4]);
        uint32_t a3 = f2tf(Abase[(gid + 8) * astride + k0 + tig + 4]);
        #pragma unroll
        for (int nt = 0; nt < 4; nt++) {
            int nb = nbase + nt * 8;
            uint32_t b0 = f2tf(Wbuf[(k0 + tig) * WSTR + nb + gid]);
            uint32_t b1 = f2tf(Wbuf[(k0 + tig + 4) * WSTR + nb + gid]);
            mma_tf32(c + nt * 4, a0, a1, a2, a3, b0, b1);
        }
    }
}

// ---------------------------------------------------------------------------
// Kernel 2: fused per (category, 16-row tile), persistent over worklist.
// smem floats: a_s 2*16*36 =1152 | w_s 2*32*264 =16896 | x_s 16*516 =8256
// total 26304 floats = 105216 B.
// ---------------------------------------------------------------------------
#define SMEM_FLOATS (2 * MT * ASTR + 2 * KC * WSTR + MT * XSTR)

__global__ __launch_bounds__(NTH, 1)
void fused_kernel(const float* __restrict__ state,
                  const float* __restrict__ obs,
                  const float* __restrict__ obs_W,
                  const float* __restrict__ obs_b,
                  const float* __restrict__ state_W,
                  const float* __restrict__ state_b,
                  const float* __restrict__ l2_W,
                  const float* __restrict__ l2_b,
                  float* __restrict__ out)
{
    extern __shared__ float sm[];
    float* a_s = sm;                       // 2 buffers of 16*ASTR
    float* w_s = a_s + 2 * MT * ASTR;      // 2 buffers of KC*WSTR
    float* x_s = w_s + 2 * KC * WSTR;      // 16 x XSTR
    __shared__ int rows_sh[MT];

    int t    = threadIdx.x;
    int lane = t & 31;
    int wid  = t >> 5;
    int gid  = lane >> 2;       // group id (row within m16)
    int tig  = lane & 3;        // thread in group
    int nbase = wid * 32;       // warp's n range [nbase, nbase+32)

    uint32_t a_u[2] = { smem_u32(a_s), smem_u32(a_s + MT * ASTR) };
    uint32_t w_u[2] = { smem_u32(w_s), smem_u32(w_s + KC * WSTR) };

    int NT = g_ntiles;
    for (int widx = blockIdx.x; widx < NT; widx += gridDim.x) {
        __syncthreads();
        int ent  = g_tiles[widx];
        int g    = ent >> 16;
        int tile = ent & 0xFFFF;
        int start = g_cat_start[g];
        int cnt   = g_cat_start[g + 1] - start;
        if (t < MT)
            rows_sh[t] = (tile * MT + t < cnt) ? g_perm[start + tile * MT + t] : -1;
        __syncthreads();

        float c[16];

        // ---- copies (FIXED: W chunk = 32x256 = 2048 float4) ----
        #define COPY_W(Wp, ch, buf) do { \
            const float* _src = (Wp) + (size_t)(ch) * KC * EMB; \
            _Pragma("unroll") \
            for (int i = t; i < 2048; i += NTH) { \
                int k = i >> 6, q = i & 63; \
                CP16(w_u[buf] + (uint32_t)(k * WSTR + q * 4) * 4, \
                     _src + k * EMB + q * 4, 16); \
            } } while (0)
        #define COPY_A(Ap, lda, ch, buf) do { \
            if (t < 128) { \
                int row = t >> 3, q = t & 7; \
                int rg = rows_sh[row]; \
                const float* _src = (Ap) + (size_t)(rg < 0 ? 0 : rg) * (lda) \
                                  + (ch) * KC + q * 4; \
                CP16(a_u[buf] + (uint32_t)(row * ASTR + q * 4) * 4, _src, \
                     rg < 0 ? 0u : 16u); \
            } } while (0)

        #define PHASE_GMEM(Ap, lda, Wp, nch) do { \
            COPY_A(Ap, lda, 0, 0); COPY_W(Wp, 0, 0); \
            asm volatile("cp.async.commit_group;"); \
            for (int ch = 0; ch < (nch); ch++) { \
                int pb = ch & 1; \
                if (ch + 1 < (nch)) { \
                    COPY_A(Ap, lda, ch + 1, pb ^ 1); \
                    COPY_W(Wp, ch + 1, pb ^ 1); \
                    asm volatile("cp.async.commit_group;"); \
                    asm volatile("cp.async.wait_group 1;"); \
                } else asm volatile("cp.async.wait_group 0;"); \
                __syncthreads(); \
                chunk_mma(a_s + pb * (MT * ASTR), ASTR, \
                          w_s + pb * (KC * WSTR), gid, tig, nbase, c); \
                __syncthreads(); \
            } } while (0)

        #define PHASE_SMEM(Wp, nch) do { \
            COPY_W(Wp, 0, 0); \
            asm volatile("cp.async.commit_group;"); \
            for (int ch = 0; ch < (nch); ch++) { \
                int pb = ch & 1; \
                if (ch + 1 < (nch)) { \
                    COPY_W(Wp, ch + 1, pb ^ 1); \
                    asm volatile("cp.async.commit_group;"); \
                    asm volatile("cp.async.wait_group 1;"); \
                } else asm volatile("cp.async.wait_group 0;"); \
                __syncthreads(); \
                chunk_mma(x_s + ch * KC, XSTR, \
                          w_s + pb * (KC * WSTR), gid, tig, nbase, c); \
                __syncthreads(); \
            } } while (0)

        // --- Phase A: state_emb = relu(state @ state_W[g] + state_b[g]) ---
        #pragma unroll
        for (int i = 0; i < 16; i++) c[i] = 0.f;
        PHASE_GMEM(state, 64, state_W + (size_t)g * 64 * EMB, 2);
        {
            const float* bs = state_b + (size_t)g * EMB;
            #pragma unroll
            for (int nt = 0; nt < 4; nt++) {
                int nb = nbase + nt * 8 + 2 * tig;
                float2 bb = *(const float2*)(bs + nb);
                float2 v0, v1;
                v0.x = fmaxf(c[nt * 4 + 0] + bb.x, 0.f);
                v0.y = fmaxf(c[nt * 4 + 1] + bb.y, 0.f);
                v1.x = fmaxf(c[nt * 4 + 2] + bb.x, 0.f);
                v1.y = fmaxf(c[nt * 4 + 3] + bb.y, 0.f);
                *(float2*)(x_s + gid * XSTR + nb)       = v0;
                *(float2*)(x_s + (gid + 8) * XSTR + nb) = v1;
            }
        }
        __syncthreads();

        // --- Phase B: obs_emb = obs @ obs_W + obs_b -> x cols [256,512) ---
        #pragma unroll
        for (int i = 0; i < 16; i++) c[i] = 0.f;
        PHASE_GMEM(obs, 512, obs_W, 16);
        {
            #pragma unroll
            for (int nt = 0; nt < 4; nt++) {
                int nb = nbase + nt * 8 + 2 * tig;
                float2 bb = *(const float2*)(obs_b + nb);
                float2 v0, v1;
                v0.x = c[nt * 4 + 0] + bb.x;
                v0.y = c[nt * 4 + 1] + bb.y;
                v1.x = c[nt * 4 + 2] + bb.x;
                v1.y = c[nt * 4 + 3] + bb.y;
                *(float2*)(x_s + gid * XSTR + 256 + nb)       = v0;
                *(float2*)(x_s + (gid + 8) * XSTR + 256 + nb) = v1;
            }
        }
        __syncthreads();

        // --- Phase C: out = x @ l2_W[g] + l2_b[g], scatter rows ---
        #pragma unroll
        for (int i = 0; i < 16; i++) c[i] = 0.f;
        PHASE_SMEM(l2_W + (size_t)g * 512 * EMB, 16);
        {
            const float* bl = l2_b + (size_t)g * EMB;
            int rg0 = rows_sh[gid];
            int rg1 = rows_sh[gid + 8];
            #pragma unroll
            for (int nt = 0; nt < 4; nt++) {
                int nb = nbase + nt * 8 + 2 * tig;
                float2 bb = *(const float2*)(bl + nb);
                if (rg0 >= 0) {
                    float2 v;
                    v.x = c[nt * 4 + 0] + bb.x;
                    v.y = c[nt * 4 + 1] + bb.y;
                    *(float2*)(out + (size_t)rg0 * EMB + nb) = v;
                }
                if (rg1 >= 0) {
                    float2 v;
                    v.x = c[nt * 4 + 2] + bb.x;
                    v.y = c[nt * 4 + 3] + bb.y;
                    *(float2*)(out + (size_t)rg1 * EMB + nb) = v;
                }
            }
        }
    }
}

// ---------------------------------------------------------------------------
extern "C" void kernel_launch(void* const* d_in, const int* in_sizes, int n_in,
                              void* d_out, int out_size) {
    const float* state   = (const float*)d_in[0];
    const float* obs     = (const float*)d_in[1];
    const int*   cat_ids = (const int*)  d_in[2];
    const float* obs_W   = (const float*)d_in[3];
    const float* obs_b   = (const float*)d_in[4];
    const float* state_W = (const float*)d_in[5];
    const float* state_b = (const float*)d_in[6];
    const float* l2_W    = (const float*)d_in[7];
    const float* l2_b    = (const float*)d_in[8];
    float* out = (float*)d_out;

    int B = in_sizes[2];

    size_t smem_bytes = SMEM_FLOATS * sizeof(float);   // 105216
    cudaFuncSetAttribute(fused_kernel,
                         cudaFuncAttributeMaxDynamicSharedMemorySize,
                         (int)smem_bytes);

    bin_kernel<<<1, 256>>>(cat_ids, B);
    fused_kernel<<<NCTAS, NTH, smem_bytes>>>(
        state, obs, obs_W, obs_b, state_W, state_b, l2_W, l2_b, out);
}